// round 6
// baseline (speedup 1.0000x reference)
#include <cuda_runtime.h>
#include <cstdint>

// Problem constants
#define B_   256
#define N_   133
#define D_   1024
#define H_   8
#define C_   128
#define MTOT (B_ * N_)        // 34048
#define NOUT 1024
#define NEG_SLOPE 0.2f

#define GTS 136               // gT row stride in floats (16B multiple)
#define PST 140               // P row stride

// ---------------- scratch (static device globals: no allocation) ----------
__device__ float gT_buf[(size_t)B_ * H_ * C_ * GTS];   // pre-cvt tf32 bits
__device__ float si_buf[H_ * MTOT];
__device__ float sj_buf[H_ * MTOT];
__device__ int   nz_cnt;
__device__ int   nz_list[N_ * N_];
__device__ float xr_buf[(size_t)MTOT * D_];            // tf32-rna rounded + k-permuted x
__device__ float wr_buf[(size_t)NOUT * D_];            // tf32-rna rounded + k-permuted W

// ---------------- helpers -------------------------------------------------
__device__ __forceinline__ uint32_t cvt_tf32(float f) {
    uint32_t r;
    asm("cvt.rna.tf32.f32 %0, %1;" : "=r"(r) : "f"(f));
    return r;
}

__device__ __forceinline__ void mma_tf32(float* d, const uint32_t* a, const uint32_t* b) {
    asm volatile(
        "mma.sync.aligned.m16n8k8.row.col.f32.tf32.tf32.f32 "
        "{%0,%1,%2,%3}, {%4,%5,%6,%7}, {%8,%9}, {%0,%1,%2,%3};\n"
        : "+f"(d[0]), "+f"(d[1]), "+f"(d[2]), "+f"(d[3])
        : "r"(a[0]), "r"(a[1]), "r"(a[2]), "r"(a[3]),
          "r"(b[0]), "r"(b[1]));
}

#define CP_ASYNC16(dst_smem_u32, src_gmem) \
    asm volatile("cp.async.ca.shared.global [%0], [%1], 16;\n" \
                 :: "r"(dst_smem_u32), "l"(src_gmem))

// =========================================================================
// pre-pass: round to tf32-rna AND permute k within each 8-group so that
// (c4, c4+4) fragment pairs become adjacent:  new_pos(k) = (k&3)*2 + (k>>2)
// out8 = {in0,in4,in1,in5,in2,in6,in3,in7}
// =========================================================================
__global__ __launch_bounds__(256)
void round_permute_kernel(const float* __restrict__ src, float* __restrict__ dst, int ngrp) {
    const int p = blockIdx.x * 256 + threadIdx.x;   // one 8-float group
    if (p < ngrp) {
        const float4* s = reinterpret_cast<const float4*>(src) + (size_t)p * 2;
        const float4 lo = s[0], hi = s[1];
        float4 o0, o1;
        o0.x = __uint_as_float(cvt_tf32(lo.x));
        o0.y = __uint_as_float(cvt_tf32(hi.x));
        o0.z = __uint_as_float(cvt_tf32(lo.y));
        o0.w = __uint_as_float(cvt_tf32(hi.y));
        o1.x = __uint_as_float(cvt_tf32(lo.z));
        o1.y = __uint_as_float(cvt_tf32(hi.z));
        o1.z = __uint_as_float(cvt_tf32(lo.w));
        o1.w = __uint_as_float(cvt_tf32(hi.w));
        float4* d = reinterpret_cast<float4*>(dst) + (size_t)p * 2;
        d[0] = o0; d[1] = o1;
    }
}

// =========================================================================
// adjacency nonzero list
// =========================================================================
__global__ void nz_zero_kernel() { nz_cnt = 0; }

__global__ __launch_bounds__(256)
void nz_build_kernel(const float* __restrict__ adj) {
    const int p = blockIdx.x * 256 + threadIdx.x;
    if (p < N_ * N_ && adj[p] != 0.f) {
        const int i = p / N_;
        const int j = p - i * N_;
        const int k = atomicAdd(&nz_cnt, 1);
        nz_list[k] = (i << 8) | j;
    }
}

// =========================================================================
// Kernel 1: g = x @ W.T  (tf32 mma.sync, pre-rounded/permuted operands,
// LDS.64 fragment loads, no cvt in mainloop) + fused epilogue
// =========================================================================
#define KC  32
#define PAD 40    // row stride: 8*r4 + 2*c4 distinct per half-warp phase -> conflict-free LDS.64
#define EST 133

__global__ __launch_bounds__(256)
void gemm1_kernel(const float* __restrict__ attn_w) {
    extern __shared__ float sm1[];
    float (*As)[128][PAD] = reinterpret_cast<float (*)[128][PAD]>(sm1);
    float (*Bs)[128][PAD] = reinterpret_cast<float (*)[128][PAD]>(sm1 + 2 * 128 * PAD);

    const int tid  = threadIdx.x;
    const int bn   = blockIdx.x;   // head
    const int bm   = blockIdx.y;
    const int lane = tid & 31;
    const int warp = tid >> 5;
    const int wm   = warp & 3;
    const int wn   = warp >> 2;

    const int lrow = tid >> 3;
    const int lc4  = (tid & 7) * 4;

    const float* xg = xr_buf + (size_t)(bm * 128) * D_ + lc4;
    const float* wg = wr_buf + (size_t)(bn * 128) * D_ + lc4;

    auto load_tiles = [&](int buf, int kc) {
#pragma unroll
        for (int it = 0; it < 4; it++) {
            int r = lrow + it * 32;
            uint32_t da = (uint32_t)__cvta_generic_to_shared(&As[buf][r][lc4]);
            CP_ASYNC16(da, xg + (size_t)r * D_ + kc);
            uint32_t db = (uint32_t)__cvta_generic_to_shared(&Bs[buf][r][lc4]);
            CP_ASYNC16(db, wg + (size_t)r * D_ + kc);
        }
        asm volatile("cp.async.commit_group;\n" ::: "memory");
    };

    float acc[2][8][4];
#pragma unroll
    for (int mt = 0; mt < 2; mt++)
#pragma unroll
        for (int nt = 0; nt < 8; nt++)
#pragma unroll
            for (int q = 0; q < 4; q++) acc[mt][nt][q] = 0.f;

    load_tiles(0, 0);

    const int r4  = lane >> 2;
    const int c4  = lane & 3;
    const int pc2 = 2 * c4;            // permuted pair column base

    for (int kc = 0; kc < D_; kc += KC) {
        int buf = (kc / KC) & 1;
        if (kc + KC < D_) {
            load_tiles(buf ^ 1, kc + KC);
            asm volatile("cp.async.wait_group 1;\n" ::: "memory");
        } else {
            asm volatile("cp.async.wait_group 0;\n" ::: "memory");
        }
        __syncthreads();

#pragma unroll
        for (int kk = 0; kk < KC / 8; kk++) {
            const int k0 = kk * 8;
            uint32_t af[2][4];
            uint32_t bf[8][2];
#pragma unroll
            for (int mt = 0; mt < 2; mt++) {
                const int rb = wm * 32 + mt * 16;
                const float2 v0 = *reinterpret_cast<const float2*>(&As[buf][rb + r4][k0 + pc2]);
                const float2 v1 = *reinterpret_cast<const float2*>(&As[buf][rb + r4 + 8][k0 + pc2]);
                af[mt][0] = __float_as_uint(v0.x);
                af[mt][1] = __float_as_uint(v1.x);
                af[mt][2] = __float_as_uint(v0.y);
                af[mt][3] = __float_as_uint(v1.y);
            }
#pragma unroll
            for (int nt = 0; nt < 8; nt++) {
                const int nb = wn * 64 + nt * 8 + r4;
                const float2 vb = *reinterpret_cast<const float2*>(&Bs[buf][nb][k0 + pc2]);
                bf[nt][0] = __float_as_uint(vb.x);
                bf[nt][1] = __float_as_uint(vb.y);
            }
#pragma unroll
            for (int mt = 0; mt < 2; mt++)
#pragma unroll
                for (int nt = 0; nt < 8; nt++)
                    mma_tf32(acc[mt][nt], af[mt], bf[nt]);
        }
        __syncthreads();
    }

    // ---------------- fused epilogue ----------------
    float* Es = sm1;   // [128][EST]
    const int c2 = (lane & 3) * 2;
#pragma unroll
    for (int mt = 0; mt < 2; mt++) {
        const int rA = wm * 32 + mt * 16 + r4;
#pragma unroll
        for (int nt = 0; nt < 8; nt++) {
            const int n0 = wn * 64 + nt * 8 + c2;
            Es[rA * EST + n0]           = acc[mt][nt][0];
            Es[rA * EST + n0 + 1]       = acc[mt][nt][1];
            Es[(rA + 8) * EST + n0]     = acc[mt][nt][2];
            Es[(rA + 8) * EST + n0 + 1] = acc[mt][nt][3];
        }
    }
    __syncthreads();

    // si/sj (full fp32 precision)
    {
        const float4 wl4 = reinterpret_cast<const float4*>(attn_w)[lane];
        const float4 wr4 = reinterpret_cast<const float4*>(attn_w + C_)[lane];
#pragma unroll
        for (int rr = 0; rr < 16; rr++) {
            const int r = warp * 16 + rr;
            const float* er = Es + r * EST + lane * 4;
            float a0 = er[0], a1 = er[1], a2 = er[2], a3 = er[3];
            float pj = a0 * wl4.x + a1 * wl4.y + a2 * wl4.z + a3 * wl4.w;
            float pi = a0 * wr4.x + a1 * wr4.y + a2 * wr4.z + a3 * wr4.w;
#pragma unroll
            for (int off = 16; off > 0; off >>= 1) {
                pj += __shfl_xor_sync(0xffffffffu, pj, off);
                pi += __shfl_xor_sync(0xffffffffu, pi, off);
            }
            if (lane == 0) {
                const int mg = bm * 128 + r;
                sj_buf[bn * MTOT + mg] = pj;
                si_buf[bn * MTOT + mg] = pi;
            }
        }
    }

    // transposed write, pre-rounded to tf32 bits
#pragma unroll
    for (int ff = 0; ff < 16; ff++) {
        const int f = warp * 16 + ff;
#pragma unroll
        for (int c = 0; c < 4; c++) {
            const int ml = c * 32 + lane;
            const float v = Es[ml * EST + f];
            const int mg = bm * 128 + ml;
            const int bb = mg / 133;
            const int nn = mg - bb * 133;
            gT_buf[((size_t)(bb * H_ + bn) * C_ + f) * GTS + nn] =
                __uint_as_float(cvt_tf32(v));
        }
    }
}

// =========================================================================
// Kernel 2 (attention): per (b,h), 512 threads
// =========================================================================
#define AKS 17

__global__ __launch_bounds__(512)
void attn_mma_kernel(float* __restrict__ out) {
    extern __shared__ float sm[];
    float* Psh  = sm;                    // [144][PST]
    float* gTs  = Psh + 144 * PST;       // [128][GTS], swizzled tf32 bits
    float* ssi  = gTs + 128 * GTS;
    float* ssj  = ssi + 144;
    float* dinv = ssj + 144;

    const int h = blockIdx.x;
    const int b = blockIdx.y;
    const int tid  = threadIdx.x;
    const int lane = tid & 31;
    const int warp = tid >> 5;

    {
        const float* gsrc = gT_buf + (size_t)(b * H_ + h) * C_ * GTS;
#pragma unroll
        for (int it = 0; it < 9; it++) {
            const int p = tid + it * 512;
            if (p < 128 * 34) {
                const int f  = p / 34;
                const int j4 = p - f * 34;
                const int sw = (j4 < 32) ? (j4 ^ ((f >> 3) & 7)) : j4;
                uint32_t dst = (uint32_t)__cvta_generic_to_shared(&gTs[f * GTS + sw * 4]);
                CP_ASYNC16(dst, gsrc + f * GTS + j4 * 4);
            }
        }
        asm volatile("cp.async.commit_group;\n" ::: "memory");
    }

    for (int i = tid; i < 144; i += 512) {
        ssi[i] = (i < N_) ? si_buf[h * MTOT + b * N_ + i] : 0.f;
        ssj[i] = (i < N_) ? sj_buf[h * MTOT + b * N_ + i] : 0.f;
    }
    {
        float4* P4 = reinterpret_cast<float4*>(Psh);
        const float4 z = make_float4(0.f, 0.f, 0.f, 0.f);
        for (int p = tid; p < 144 * PST / 4; p += 512) P4[p] = z;
    }
    const int nnz = nz_cnt;
    __syncthreads();

    for (int e = tid; e < nnz; e += 512) {
        const int pk = nz_list[e];
        const int i  = pk >> 8;
        const int j  = pk & 255;
        float v = ssi[i] + ssj[j];
        v = (v > 0.f) ? v : NEG_SLOPE * v;
        Psh[i * PST + j] = __expf(v);
    }
    __syncthreads();

    for (int j = tid; j < N_; j += 512) {
        float s = 0.f;
#pragma unroll 7
        for (int i = 0; i < N_; i++) s += Psh[i * PST + j];
        dinv[j] = 1.0f / s;
    }
    __syncthreads();

    for (int e = tid; e < nnz; e += 512) {
        const int pk = nz_list[e];
        const int i  = pk >> 8;
        const int j  = pk & 255;
        Psh[i * PST + j] = __uint_as_float(cvt_tf32(Psh[i * PST + j] * dinv[j]));
    }

    asm volatile("cp.async.wait_group 0;\n" ::: "memory");
    __syncthreads();

    const int wm = warp & 3;
    const int wn = warp >> 2;
    const int r4 = lane >> 2;
    const int c4 = lane & 3;

    float acc[3][4][4];
#pragma unroll
    for (int mi = 0; mi < 3; mi++)
#pragma unroll
        for (int nt = 0; nt < 4; nt++)
#pragma unroll
            for (int q = 0; q < 4; q++) acc[mi][nt][q] = 0.f;

#pragma unroll
    for (int ks = 0; ks < AKS; ks++) {
        const int ka  = ks * 8 + c4;
        const int kb  = ka + 4;
        const int j4a = 2 * ks;
        const int j4b = 2 * ks + 1;
        uint32_t bf[4][2];
#pragma unroll
        for (int nt = 0; nt < 4; nt++) {
            const int n   = wn * 32 + nt * 8 + r4;
            const int key = (n >> 3) & 7;
            const int sa  = (j4a < 32) ? (j4a ^ key) : j4a;
            const int sb  = (j4b < 32) ? (j4b ^ key) : j4b;
            bf[nt][0] = __float_as_uint(gTs[n * GTS + sa * 4 + (ka & 3)]);
            bf[nt][1] = __float_as_uint(gTs[n * GTS + sb * 4 + (kb & 3)]);
        }
#pragma unroll
        for (int mi = 0; mi < 3; mi++) {
            const int mt = wm + mi * 4;
            if (mt >= 9) break;
            const int m0 = mt * 16;
            uint32_t af[4];
            af[0] = __float_as_uint(Psh[(m0 + r4) * PST + ka]);
            af[1] = __float_as_uint(Psh[(m0 + r4 + 8) * PST + ka]);
            af[2] = __float_as_uint(Psh[(m0 + r4) * PST + kb]);
            af[3] = __float_as_uint(Psh[(m0 + r4 + 8) * PST + kb]);
#pragma unroll
            for (int nt = 0; nt < 4; nt++)
                mma_tf32(acc[mi][nt], af, bf[nt]);
        }
    }

    const int c2 = c4 * 2;
#pragma unroll
    for (int mi = 0; mi < 3; mi++) {
        const int mt = wm + mi * 4;
        if (mt >= 9) break;
        const int i1 = mt * 16 + r4;
        const int i2 = i1 + 8;
#pragma unroll
        for (int nt = 0; nt < 4; nt++) {
            const int f0 = wn * 32 + nt * 8 + c2;
            if (i1 < N_) {
                float2 v = make_float2(acc[mi][nt][0], acc[mi][nt][1]);
                *reinterpret_cast<float2*>(out + (size_t)(b * N_ + i1) * NOUT + h * C_ + f0) = v;
            }
            if (i2 < N_) {
                float2 v = make_float2(acc[mi][nt][2], acc[mi][nt][3]);
                *reinterpret_cast<float2*>(out + (size_t)(b * N_ + i2) * NOUT + h * C_ + f0) = v;
            }
        }
    }
}

// =========================================================================
// launch
// =========================================================================
extern "C" void kernel_launch(void* const* d_in, const int* in_sizes, int n_in,
                              void* d_out, int out_size) {
    const float* x      = (const float*)d_in[0];
    const float* W      = (const float*)d_in[1];
    const float* attn_w = (const float*)d_in[2];
    const float* adj    = (const float*)d_in[3];
    float* out          = (float*)d_out;

    const int smem1 = 2 * 128 * PAD * 2 * sizeof(float);                     // 81920 B
    const int smem3 = (144 * PST + 128 * GTS + 3 * 144) * sizeof(float);     // ~152 KB

    cudaFuncSetAttribute(gemm1_kernel,    cudaFuncAttributeMaxDynamicSharedMemorySize, smem1);
    cudaFuncSetAttribute(attn_mma_kernel, cudaFuncAttributeMaxDynamicSharedMemorySize, smem3);

    // pre-round + permute x and W
    {
        float* xr; cudaGetSymbolAddress((void**)&xr, xr_buf);
        float* wr; cudaGetSymbolAddress((void**)&wr, wr_buf);
        const int ngx = (int)((size_t)MTOT * D_ / 8);
        const int ngw = (int)((size_t)NOUT * D_ / 8);
        round_permute_kernel<<<(ngx + 255) / 256, 256>>>(x, xr, ngx);
        round_permute_kernel<<<(ngw + 255) / 256, 256>>>(W, wr, ngw);
    }

    nz_zero_kernel<<<1, 1>>>();
    nz_build_kernel<<<(N_ * N_ + 255) / 256, 256>>>(adj);

    dim3 g1(H_, MTOT / 128);   // (8 heads, 266 row tiles)
    gemm1_kernel<<<g1, 256, smem1>>>(attn_w);

    dim3 g3(H_, B_);
    attn_mma_kernel<<<g3, 512, smem3>>>(out);
}

// round 9
// speedup vs baseline: 1.0413x; 1.0413x over previous
#include <cuda_runtime.h>
#include <cstdint>

// Problem constants
#define B_   256
#define N_   133
#define D_   1024
#define H_   8
#define C_   128
#define MTOT (B_ * N_)        // 34048
#define NOUT 1024
#define NEG_SLOPE 0.2f

#define GTS 136               // gT row stride in floats (16B multiple)
#define PST 140               // P row stride

// ---------------- scratch (static device globals: no allocation) ----------
__device__ float gT_buf[(size_t)B_ * H_ * C_ * GTS];   // pre-cvt tf32 bits
__device__ float si_buf[H_ * MTOT];
__device__ float sj_buf[H_ * MTOT];
__device__ int   nz_cnt;
__device__ int   nz_list[N_ * N_];

// ---------------- helpers -------------------------------------------------
__device__ __forceinline__ uint32_t cvt_tf32(float f) {
    uint32_t r;
    asm("cvt.rna.tf32.f32 %0, %1;" : "=r"(r) : "f"(f));
    return r;
}

__device__ __forceinline__ void mma_tf32(float* d, const uint32_t* a, const uint32_t* b) {
    asm volatile(
        "mma.sync.aligned.m16n8k8.row.col.f32.tf32.tf32.f32 "
        "{%0,%1,%2,%3}, {%4,%5,%6,%7}, {%8,%9}, {%0,%1,%2,%3};\n"
        : "+f"(d[0]), "+f"(d[1]), "+f"(d[2]), "+f"(d[3])
        : "r"(a[0]), "r"(a[1]), "r"(a[2]), "r"(a[3]),
          "r"(b[0]), "r"(b[1]));
}

#define CP_ASYNC16(dst_smem_u32, src_gmem) \
    asm volatile("cp.async.ca.shared.global [%0], [%1], 16;\n" \
                 :: "r"(dst_smem_u32), "l"(src_gmem))

// =========================================================================
// adjacency nonzero list
// =========================================================================
__global__ void nz_zero_kernel() { nz_cnt = 0; }

__global__ __launch_bounds__(256)
void nz_build_kernel(const float* __restrict__ adj) {
    const int p = blockIdx.x * 256 + threadIdx.x;
    if (p < N_ * N_ && adj[p] != 0.f) {
        const int i = p / N_;
        const int j = p - i * N_;
        const int k = atomicAdd(&nz_cnt, 1);
        nz_list[k] = (i << 8) | j;
    }
}

// =========================================================================
// Kernel 1: g = x @ W.T  (tf32 mma.sync, 128x128 block tile, 64x64 WARP tile,
// 128 threads / 4 warps) + fused epilogue (si/sj + transposed tf32 gT write)
// =========================================================================
#define KC  32
#define PAD 36
#define EST 133

__global__ __launch_bounds__(128)
void gemm1_kernel(const float* __restrict__ x, const float* __restrict__ W,
                  const float* __restrict__ attn_w) {
    extern __shared__ float sm1[];
    float (*As)[128][PAD] = reinterpret_cast<float (*)[128][PAD]>(sm1);
    float (*Bs)[128][PAD] = reinterpret_cast<float (*)[128][PAD]>(sm1 + 2 * 128 * PAD);

    const int tid  = threadIdx.x;
    const int bn   = blockIdx.x;   // head
    const int bm   = blockIdx.y;
    const int lane = tid & 31;
    const int warp = tid >> 5;     // 0..3
    const int wm   = warp & 1;     // M half (64 rows)
    const int wn   = warp >> 1;    // N half (64 cols)

    const int lrow = tid >> 3;        // 0..15
    const int lc4  = (tid & 7) * 4;   // 0..28

    const float* xg = x + (size_t)(bm * 128) * D_ + lc4;
    const float* wg = W + (size_t)(bn * 128) * D_ + lc4;

    auto load_tiles = [&](int buf, int kc) {
#pragma unroll
        for (int it = 0; it < 8; it++) {
            int r = lrow + it * 16;
            uint32_t da = (uint32_t)__cvta_generic_to_shared(&As[buf][r][lc4]);
            CP_ASYNC16(da, xg + (size_t)r * D_ + kc);
            uint32_t db = (uint32_t)__cvta_generic_to_shared(&Bs[buf][r][lc4]);
            CP_ASYNC16(db, wg + (size_t)r * D_ + kc);
        }
        asm volatile("cp.async.commit_group;\n" ::: "memory");
    };

    float acc[4][8][4];
#pragma unroll
    for (int mt = 0; mt < 4; mt++)
#pragma unroll
        for (int nt = 0; nt < 8; nt++)
#pragma unroll
            for (int q = 0; q < 4; q++) acc[mt][nt][q] = 0.f;

    load_tiles(0, 0);

    const int r4 = lane >> 2;
    const int c4 = lane & 3;

    for (int kc = 0; kc < D_; kc += KC) {
        int buf = (kc / KC) & 1;
        if (kc + KC < D_) {
            load_tiles(buf ^ 1, kc + KC);
            asm volatile("cp.async.wait_group 1;\n" ::: "memory");
        } else {
            asm volatile("cp.async.wait_group 0;\n" ::: "memory");
        }
        __syncthreads();

#pragma unroll
        for (int kk = 0; kk < KC / 8; kk++) {
            const int k0 = kk * 8;
            uint32_t af[4][4];
            uint32_t bf[8][2];
#pragma unroll
            for (int mt = 0; mt < 4; mt++) {
                const int rb = wm * 64 + mt * 16;
                af[mt][0] = cvt_tf32(As[buf][rb + r4][k0 + c4]);
                af[mt][1] = cvt_tf32(As[buf][rb + r4 + 8][k0 + c4]);
                af[mt][2] = cvt_tf32(As[buf][rb + r4][k0 + c4 + 4]);
                af[mt][3] = cvt_tf32(As[buf][rb + r4 + 8][k0 + c4 + 4]);
            }
#pragma unroll
            for (int nt = 0; nt < 8; nt++) {
                const int nb = wn * 64 + nt * 8 + r4;
                bf[nt][0] = cvt_tf32(Bs[buf][nb][k0 + c4]);
                bf[nt][1] = cvt_tf32(Bs[buf][nb][k0 + c4 + 4]);
            }
#pragma unroll
            for (int mt = 0; mt < 4; mt++)
#pragma unroll
                for (int nt = 0; nt < 8; nt++)
                    mma_tf32(acc[mt][nt], af[mt], bf[nt]);
        }
        __syncthreads();
    }

    // ---------------- fused epilogue ----------------
    float* Es = sm1;   // [128][EST]
    const int c2 = (lane & 3) * 2;
#pragma unroll
    for (int mt = 0; mt < 4; mt++) {
        const int rA = wm * 64 + mt * 16 + r4;
#pragma unroll
        for (int nt = 0; nt < 8; nt++) {
            const int n0 = wn * 64 + nt * 8 + c2;
            Es[rA * EST + n0]           = acc[mt][nt][0];
            Es[rA * EST + n0 + 1]       = acc[mt][nt][1];
            Es[(rA + 8) * EST + n0]     = acc[mt][nt][2];
            Es[(rA + 8) * EST + n0 + 1] = acc[mt][nt][3];
        }
    }
    __syncthreads();

    // si/sj (full fp32 precision): 32 rows per warp
    {
        const float4 wl4 = reinterpret_cast<const float4*>(attn_w)[lane];
        const float4 wr4 = reinterpret_cast<const float4*>(attn_w + C_)[lane];
#pragma unroll
        for (int rr = 0; rr < 32; rr++) {
            const int r = warp * 32 + rr;
            const float* er = Es + r * EST + lane * 4;
            float a0 = er[0], a1 = er[1], a2 = er[2], a3 = er[3];
            float pj = a0 * wl4.x + a1 * wl4.y + a2 * wl4.z + a3 * wl4.w;
            float pi = a0 * wr4.x + a1 * wr4.y + a2 * wr4.z + a3 * wr4.w;
#pragma unroll
            for (int off = 16; off > 0; off >>= 1) {
                pj += __shfl_xor_sync(0xffffffffu, pj, off);
                pi += __shfl_xor_sync(0xffffffffu, pi, off);
            }
            if (lane == 0) {
                const int mg = bm * 128 + r;
                sj_buf[bn * MTOT + mg] = pj;
                si_buf[bn * MTOT + mg] = pi;
            }
        }
    }

    // transposed write, pre-rounded to tf32 bits: 32 f-columns per warp
#pragma unroll
    for (int ff = 0; ff < 32; ff++) {
        const int f = warp * 32 + ff;
#pragma unroll
        for (int c = 0; c < 4; c++) {
            const int ml = c * 32 + lane;
            const float v = Es[ml * EST + f];
            const int mg = bm * 128 + ml;
            const int bb = mg / 133;
            const int nn = mg - bb * 133;
            gT_buf[((size_t)(bb * H_ + bn) * C_ + f) * GTS + nn] =
                __uint_as_float(cvt_tf32(v));
        }
    }
}

// =========================================================================
// Kernel 2 (attention): per (b,h), 512 threads  (unchanged from R4)
// =========================================================================
#define AKS 17

__global__ __launch_bounds__(512)
void attn_mma_kernel(float* __restrict__ out) {
    extern __shared__ float sm[];
    float* Psh  = sm;                    // [144][PST]
    float* gTs  = Psh + 144 * PST;       // [128][GTS], swizzled tf32 bits
    float* ssi  = gTs + 128 * GTS;
    float* ssj  = ssi + 144;
    float* dinv = ssj + 144;

    const int h = blockIdx.x;
    const int b = blockIdx.y;
    const int tid  = threadIdx.x;
    const int lane = tid & 31;
    const int warp = tid >> 5;

    {
        const float* gsrc = gT_buf + (size_t)(b * H_ + h) * C_ * GTS;
#pragma unroll
        for (int it = 0; it < 9; it++) {
            const int p = tid + it * 512;
            if (p < 128 * 34) {
                const int f  = p / 34;
                const int j4 = p - f * 34;
                const int sw = (j4 < 32) ? (j4 ^ ((f >> 3) & 7)) : j4;
                uint32_t dst = (uint32_t)__cvta_generic_to_shared(&gTs[f * GTS + sw * 4]);
                CP_ASYNC16(dst, gsrc + f * GTS + j4 * 4);
            }
        }
        asm volatile("cp.async.commit_group;\n" ::: "memory");
    }

    for (int i = tid; i < 144; i += 512) {
        ssi[i] = (i < N_) ? si_buf[h * MTOT + b * N_ + i] : 0.f;
        ssj[i] = (i < N_) ? sj_buf[h * MTOT + b * N_ + i] : 0.f;
    }
    {
        float4* P4 = reinterpret_cast<float4*>(Psh);
        const float4 z = make_float4(0.f, 0.f, 0.f, 0.f);
        for (int p = tid; p < 144 * PST / 4; p += 512) P4[p] = z;
    }
    const int nnz = nz_cnt;
    __syncthreads();

    for (int e = tid; e < nnz; e += 512) {
        const int pk = nz_list[e];
        const int i  = pk >> 8;
        const int j  = pk & 255;
        float v = ssi[i] + ssj[j];
        v = (v > 0.f) ? v : NEG_SLOPE * v;
        Psh[i * PST + j] = __expf(v);
    }
    __syncthreads();

    for (int j = tid; j < N_; j += 512) {
        float s = 0.f;
#pragma unroll 7
        for (int i = 0; i < N_; i++) s += Psh[i * PST + j];
        dinv[j] = 1.0f / s;
    }
    __syncthreads();

    for (int e = tid; e < nnz; e += 512) {
        const int pk = nz_list[e];
        const int i  = pk >> 8;
        const int j  = pk & 255;
        Psh[i * PST + j] = __uint_as_float(cvt_tf32(Psh[i * PST + j] * dinv[j]));
    }

    asm volatile("cp.async.wait_group 0;\n" ::: "memory");
    __syncthreads();

    const int wm = warp & 3;
    const int wn = warp >> 2;
    const int r4 = lane >> 2;
    const int c4 = lane & 3;

    float acc[3][4][4];
#pragma unroll
    for (int mi = 0; mi < 3; mi++)
#pragma unroll
        for (int nt = 0; nt < 4; nt++)
#pragma unroll
            for (int q = 0; q < 4; q++) acc[mi][nt][q] = 0.f;

#pragma unroll
    for (int ks = 0; ks < AKS; ks++) {
        const int ka  = ks * 8 + c4;
        const int kb  = ka + 4;
        const int j4a = 2 * ks;
        const int j4b = 2 * ks + 1;
        uint32_t bf[4][2];
#pragma unroll
        for (int nt = 0; nt < 4; nt++) {
            const int n   = wn * 32 + nt * 8 + r4;
            const int key = (n >> 3) & 7;
            const int sa  = (j4a < 32) ? (j4a ^ key) : j4a;
            const int sb  = (j4b < 32) ? (j4b ^ key) : j4b;
            bf[nt][0] = __float_as_uint(gTs[n * GTS + sa * 4 + (ka & 3)]);
            bf[nt][1] = __float_as_uint(gTs[n * GTS + sb * 4 + (kb & 3)]);
        }
#pragma unroll
        for (int mi = 0; mi < 3; mi++) {
            const int mt = wm + mi * 4;
            if (mt >= 9) break;
            const int m0 = mt * 16;
            uint32_t af[4];
            af[0] = __float_as_uint(Psh[(m0 + r4) * PST + ka]);
            af[1] = __float_as_uint(Psh[(m0 + r4 + 8) * PST + ka]);
            af[2] = __float_as_uint(Psh[(m0 + r4) * PST + kb]);
            af[3] = __float_as_uint(Psh[(m0 + r4 + 8) * PST + kb]);
#pragma unroll
            for (int nt = 0; nt < 4; nt++)
                mma_tf32(acc[mi][nt], af, bf[nt]);
        }
    }

    const int c2 = c4 * 2;
#pragma unroll
    for (int mi = 0; mi < 3; mi++) {
        const int mt = wm + mi * 4;
        if (mt >= 9) break;
        const int i1 = mt * 16 + r4;
        const int i2 = i1 + 8;
#pragma unroll
        for (int nt = 0; nt < 4; nt++) {
            const int f0 = wn * 32 + nt * 8 + c2;
            if (i1 < N_) {
                float2 v = make_float2(acc[mi][nt][0], acc[mi][nt][1]);
                *reinterpret_cast<float2*>(out + (size_t)(b * N_ + i1) * NOUT + h * C_ + f0) = v;
            }
            if (i2 < N_) {
                float2 v = make_float2(acc[mi][nt][2], acc[mi][nt][3]);
                *reinterpret_cast<float2*>(out + (size_t)(b * N_ + i2) * NOUT + h * C_ + f0) = v;
            }
        }
    }
}

// =========================================================================
// launch
// =========================================================================
extern "C" void kernel_launch(void* const* d_in, const int* in_sizes, int n_in,
                              void* d_out, int out_size) {
    const float* x      = (const float*)d_in[0];
    const float* W      = (const float*)d_in[1];
    const float* attn_w = (const float*)d_in[2];
    const float* adj    = (const float*)d_in[3];
    float* out          = (float*)d_out;

    const int smem1 = 2 * 128 * PAD * 2 * sizeof(float);                     // 73728 B
    const int smem3 = (144 * PST + 128 * GTS + 3 * 144) * sizeof(float);     // ~152 KB

    cudaFuncSetAttribute(gemm1_kernel,    cudaFuncAttributeMaxDynamicSharedMemorySize, smem1);
    cudaFuncSetAttribute(attn_mma_kernel, cudaFuncAttributeMaxDynamicSharedMemorySize, smem3);

    nz_zero_kernel<<<1, 1>>>();
    nz_build_kernel<<<(N_ * N_ + 255) / 256, 256>>>(adj);

    dim3 g1(H_, MTOT / 128);   // (8 heads, 266 row tiles)
    gemm1_kernel<<<g1, 128, smem1>>>(x, W, attn_w);

    dim3 g3(H_, B_);
    attn_mma_kernel<<<g3, 512, smem3>>>(out);
}

// round 10
// speedup vs baseline: 1.0838x; 1.0408x over previous
#include <cuda_runtime.h>
#include <cstdint>

// Problem constants
#define B_   256
#define N_   133
#define D_   1024
#define H_   8
#define C_   128
#define MTOT (B_ * N_)        // 34048
#define NOUT 1024
#define NEG_SLOPE 0.2f

#define GTS 136               // gT row stride in floats (16B multiple)
#define PST 140               // P row stride

// ---------------- scratch (static device globals: no allocation) ----------
__device__ float gT_buf[(size_t)B_ * H_ * C_ * GTS];   // pre-cvt tf32 bits
__device__ float si_buf[H_ * MTOT];
__device__ float sj_buf[H_ * MTOT];
__device__ int   nz_cnt;
__device__ int   nz_list[N_ * N_];

// ---------------- helpers -------------------------------------------------
__device__ __forceinline__ uint32_t cvt_tf32(float f) {
    uint32_t r;
    asm("cvt.rna.tf32.f32 %0, %1;" : "=r"(r) : "f"(f));
    return r;
}

__device__ __forceinline__ void mma_tf32(float* d, const uint32_t* a, const uint32_t* b) {
    asm volatile(
        "mma.sync.aligned.m16n8k8.row.col.f32.tf32.tf32.f32 "
        "{%0,%1,%2,%3}, {%4,%5,%6,%7}, {%8,%9}, {%0,%1,%2,%3};\n"
        : "+f"(d[0]), "+f"(d[1]), "+f"(d[2]), "+f"(d[3])
        : "r"(a[0]), "r"(a[1]), "r"(a[2]), "r"(a[3]),
          "r"(b[0]), "r"(b[1]));
}

#define CP_ASYNC16(dst_smem_u32, src_gmem) \
    asm volatile("cp.async.ca.shared.global [%0], [%1], 16;\n" \
                 :: "r"(dst_smem_u32), "l"(src_gmem))

// =========================================================================
// adjacency nonzero list
// =========================================================================
__global__ void nz_zero_kernel() { nz_cnt = 0; }

__global__ __launch_bounds__(256)
void nz_build_kernel(const float* __restrict__ adj) {
    const int p = blockIdx.x * 256 + threadIdx.x;
    if (p < N_ * N_ && adj[p] != 0.f) {
        const int i = p / N_;
        const int j = p - i * N_;
        const int k = atomicAdd(&nz_cnt, 1);
        nz_list[k] = (i << 8) | j;
    }
}

// =========================================================================
// Kernel 1: g = x @ W.T  (tf32 mma.sync, 128x128 block tile, 32x64 warp tile,
// 256 threads) with register-double-buffered (software-pipelined) fragment
// loads + fused epilogue (si/sj + transposed tf32 gT write)
// =========================================================================
#define KC  32
#define PAD 36
#define EST 133

__global__ __launch_bounds__(256, 2)
void gemm1_kernel(const float* __restrict__ x, const float* __restrict__ W,
                  const float* __restrict__ attn_w) {
    extern __shared__ float sm1[];
    float (*As)[128][PAD] = reinterpret_cast<float (*)[128][PAD]>(sm1);
    float (*Bs)[128][PAD] = reinterpret_cast<float (*)[128][PAD]>(sm1 + 2 * 128 * PAD);

    const int tid  = threadIdx.x;
    const int bn   = blockIdx.x;   // head
    const int bm   = blockIdx.y;
    const int lane = tid & 31;
    const int warp = tid >> 5;
    const int wm   = warp & 3;
    const int wn   = warp >> 2;

    const int lrow = tid >> 3;
    const int lc4  = (tid & 7) * 4;

    const float* xg = x + (size_t)(bm * 128) * D_ + lc4;
    const float* wg = W + (size_t)(bn * 128) * D_ + lc4;

    auto load_tiles = [&](int buf, int kc) {
#pragma unroll
        for (int it = 0; it < 4; it++) {
            int r = lrow + it * 32;
            uint32_t da = (uint32_t)__cvta_generic_to_shared(&As[buf][r][lc4]);
            CP_ASYNC16(da, xg + (size_t)r * D_ + kc);
            uint32_t db = (uint32_t)__cvta_generic_to_shared(&Bs[buf][r][lc4]);
            CP_ASYNC16(db, wg + (size_t)r * D_ + kc);
        }
        asm volatile("cp.async.commit_group;\n" ::: "memory");
    };

    float acc[2][8][4];
#pragma unroll
    for (int mt = 0; mt < 2; mt++)
#pragma unroll
        for (int nt = 0; nt < 8; nt++)
#pragma unroll
            for (int q = 0; q < 4; q++) acc[mt][nt][q] = 0.f;

    load_tiles(0, 0);

    const int r4 = lane >> 2;
    const int c4 = lane & 3;

    // register fragment double buffers
    uint32_t af[2][2][4];
    uint32_t bf[2][8][2];

    auto load_frags = [&](int pb, int buf, int k0) {
#pragma unroll
        for (int mt = 0; mt < 2; mt++) {
            const int rb = wm * 32 + mt * 16;
            af[pb][mt][0] = cvt_tf32(As[buf][rb + r4][k0 + c4]);
            af[pb][mt][1] = cvt_tf32(As[buf][rb + r4 + 8][k0 + c4]);
            af[pb][mt][2] = cvt_tf32(As[buf][rb + r4][k0 + c4 + 4]);
            af[pb][mt][3] = cvt_tf32(As[buf][rb + r4 + 8][k0 + c4 + 4]);
        }
#pragma unroll
        for (int nt = 0; nt < 8; nt++) {
            const int nb = wn * 64 + nt * 8 + r4;
            bf[pb][nt][0] = cvt_tf32(Bs[buf][nb][k0 + c4]);
            bf[pb][nt][1] = cvt_tf32(Bs[buf][nb][k0 + c4 + 4]);
        }
    };

    for (int kc = 0; kc < D_; kc += KC) {
        int buf = (kc / KC) & 1;
        if (kc + KC < D_) {
            load_tiles(buf ^ 1, kc + KC);
            asm volatile("cp.async.wait_group 1;\n" ::: "memory");
        } else {
            asm volatile("cp.async.wait_group 0;\n" ::: "memory");
        }
        __syncthreads();

        // software-pipelined k8 steps: load k+1 frags while issuing k's MMAs
        load_frags(0, buf, 0);
#pragma unroll
        for (int kk = 0; kk < KC / 8; kk++) {
            const int pb = kk & 1;
            if (kk < KC / 8 - 1) load_frags(pb ^ 1, buf, (kk + 1) * 8);
#pragma unroll
            for (int mt = 0; mt < 2; mt++)
#pragma unroll
                for (int nt = 0; nt < 8; nt++)
                    mma_tf32(acc[mt][nt], af[pb][mt], bf[pb][nt]);
        }
        __syncthreads();
    }

    // ---------------- fused epilogue ----------------
    float* Es = sm1;   // [128][EST]
    const int c2 = (lane & 3) * 2;
#pragma unroll
    for (int mt = 0; mt < 2; mt++) {
        const int rA = wm * 32 + mt * 16 + r4;
#pragma unroll
        for (int nt = 0; nt < 8; nt++) {
            const int n0 = wn * 64 + nt * 8 + c2;
            Es[rA * EST + n0]           = acc[mt][nt][0];
            Es[rA * EST + n0 + 1]       = acc[mt][nt][1];
            Es[(rA + 8) * EST + n0]     = acc[mt][nt][2];
            Es[(rA + 8) * EST + n0 + 1] = acc[mt][nt][3];
        }
    }
    __syncthreads();

    // si/sj (full fp32 precision)
    {
        const float4 wl4 = reinterpret_cast<const float4*>(attn_w)[lane];
        const float4 wr4 = reinterpret_cast<const float4*>(attn_w + C_)[lane];
#pragma unroll
        for (int rr = 0; rr < 16; rr++) {
            const int r = warp * 16 + rr;
            const float* er = Es + r * EST + lane * 4;
            float a0 = er[0], a1 = er[1], a2 = er[2], a3 = er[3];
            float pj = a0 * wl4.x + a1 * wl4.y + a2 * wl4.z + a3 * wl4.w;
            float pi = a0 * wr4.x + a1 * wr4.y + a2 * wr4.z + a3 * wr4.w;
#pragma unroll
            for (int off = 16; off > 0; off >>= 1) {
                pj += __shfl_xor_sync(0xffffffffu, pj, off);
                pi += __shfl_xor_sync(0xffffffffu, pi, off);
            }
            if (lane == 0) {
                const int mg = bm * 128 + r;
                sj_buf[bn * MTOT + mg] = pj;
                si_buf[bn * MTOT + mg] = pi;
            }
        }
    }

    // transposed write, pre-rounded to tf32 bits
#pragma unroll
    for (int ff = 0; ff < 16; ff++) {
        const int f = warp * 16 + ff;
#pragma unroll
        for (int c = 0; c < 4; c++) {
            const int ml = c * 32 + lane;
            const float v = Es[ml * EST + f];
            const int mg = bm * 128 + ml;
            const int bb = mg / 133;
            const int nn = mg - bb * 133;
            gT_buf[((size_t)(bb * H_ + bn) * C_ + f) * GTS + nn] =
                __uint_as_float(cvt_tf32(v));
        }
    }
}

// =========================================================================
// Kernel 2 (attention): per (b,h), 512 threads  (R4 config, unchanged)
// =========================================================================
#define AKS 17

__global__ __launch_bounds__(512)
void attn_mma_kernel(float* __restrict__ out) {
    extern __shared__ float sm[];
    float* Psh  = sm;                    // [144][PST]
    float* gTs  = Psh + 144 * PST;       // [128][GTS], swizzled tf32 bits
    float* ssi  = gTs + 128 * GTS;
    float* ssj  = ssi + 144;
    float* dinv = ssj + 144;

    const int h = blockIdx.x;
    const int b = blockIdx.y;
    const int tid  = threadIdx.x;
    const int lane = tid & 31;
    const int warp = tid >> 5;

    {
        const float* gsrc = gT_buf + (size_t)(b * H_ + h) * C_ * GTS;
#pragma unroll
        for (int it = 0; it < 9; it++) {
            const int p = tid + it * 512;
            if (p < 128 * 34) {
                const int f  = p / 34;
                const int j4 = p - f * 34;
                const int sw = (j4 < 32) ? (j4 ^ ((f >> 3) & 7)) : j4;
                uint32_t dst = (uint32_t)__cvta_generic_to_shared(&gTs[f * GTS + sw * 4]);
                CP_ASYNC16(dst, gsrc + f * GTS + j4 * 4);
            }
        }
        asm volatile("cp.async.commit_group;\n" ::: "memory");
    }

    for (int i = tid; i < 144; i += 512) {
        ssi[i] = (i < N_) ? si_buf[h * MTOT + b * N_ + i] : 0.f;
        ssj[i] = (i < N_) ? sj_buf[h * MTOT + b * N_ + i] : 0.f;
    }
    {
        float4* P4 = reinterpret_cast<float4*>(Psh);
        const float4 z = make_float4(0.f, 0.f, 0.f, 0.f);
        for (int p = tid; p < 144 * PST / 4; p += 512) P4[p] = z;
    }
    const int nnz = nz_cnt;
    __syncthreads();

    for (int e = tid; e < nnz; e += 512) {
        const int pk = nz_list[e];
        const int i  = pk >> 8;
        const int j  = pk & 255;
        float v = ssi[i] + ssj[j];
        v = (v > 0.f) ? v : NEG_SLOPE * v;
        Psh[i * PST + j] = __expf(v);
    }
    __syncthreads();

    for (int j = tid; j < N_; j += 512) {
        float s = 0.f;
#pragma unroll 7
        for (int i = 0; i < N_; i++) s += Psh[i * PST + j];
        dinv[j] = 1.0f / s;
    }
    __syncthreads();

    for (int e = tid; e < nnz; e += 512) {
        const int pk = nz_list[e];
        const int i  = pk >> 8;
        const int j  = pk & 255;
        Psh[i * PST + j] = __uint_as_float(cvt_tf32(Psh[i * PST + j] * dinv[j]));
    }

    asm volatile("cp.async.wait_group 0;\n" ::: "memory");
    __syncthreads();

    const int wm = warp & 3;
    const int wn = warp >> 2;
    const int r4 = lane >> 2;
    const int c4 = lane & 3;

    float acc[3][4][4];
#pragma unroll
    for (int mi = 0; mi < 3; mi++)
#pragma unroll
        for (int nt = 0; nt < 4; nt++)
#pragma unroll
            for (int q = 0; q < 4; q++) acc[mi][nt][q] = 0.f;

#pragma unroll
    for (int ks = 0; ks < AKS; ks++) {
        const int ka  = ks * 8 + c4;
        const int kb  = ka + 4;
        const int j4a = 2 * ks;
        const int j4b = 2 * ks + 1;
        uint32_t bf[4][2];
#pragma unroll
        for (int nt = 0; nt < 4; nt++) {
            const int n   = wn * 32 + nt * 8 + r4;
            const int key = (n >> 3) & 7;
            const int sa  = (j4a < 32) ? (j4a ^ key) : j4a;
            const int sb  = (j4b < 32) ? (j4b ^ key) : j4b;
            bf[nt][0] = __float_as_uint(gTs[n * GTS + sa * 4 + (ka & 3)]);
            bf[nt][1] = __float_as_uint(gTs[n * GTS + sb * 4 + (kb & 3)]);
        }
#pragma unroll
        for (int mi = 0; mi < 3; mi++) {
            const int mt = wm + mi * 4;
            if (mt >= 9) break;
            const int m0 = mt * 16;
            uint32_t af[4];
            af[0] = __float_as_uint(Psh[(m0 + r4) * PST + ka]);
            af[1] = __float_as_uint(Psh[(m0 + r4 + 8) * PST + ka]);
            af[2] = __float_as_uint(Psh[(m0 + r4) * PST + kb]);
            af[3] = __float_as_uint(Psh[(m0 + r4 + 8) * PST + kb]);
#pragma unroll
            for (int nt = 0; nt < 4; nt++)
                mma_tf32(acc[mi][nt], af, bf[nt]);
        }
    }

    const int c2 = c4 * 2;
#pragma unroll
    for (int mi = 0; mi < 3; mi++) {
        const int mt = wm + mi * 4;
        if (mt >= 9) break;
        const int i1 = mt * 16 + r4;
        const int i2 = i1 + 8;
#pragma unroll
        for (int nt = 0; nt < 4; nt++) {
            const int f0 = wn * 32 + nt * 8 + c2;
            if (i1 < N_) {
                float2 v = make_float2(acc[mi][nt][0], acc[mi][nt][1]);
                *reinterpret_cast<float2*>(out + (size_t)(b * N_ + i1) * NOUT + h * C_ + f0) = v;
            }
            if (i2 < N_) {
                float2 v = make_float2(acc[mi][nt][2], acc[mi][nt][3]);
                *reinterpret_cast<float2*>(out + (size_t)(b * N_ + i2) * NOUT + h * C_ + f0) = v;
            }
        }
    }
}

// =========================================================================
// launch
// =========================================================================
extern "C" void kernel_launch(void* const* d_in, const int* in_sizes, int n_in,
                              void* d_out, int out_size) {
    const float* x      = (const float*)d_in[0];
    const float* W      = (const float*)d_in[1];
    const float* attn_w = (const float*)d_in[2];
    const float* adj    = (const float*)d_in[3];
    float* out          = (float*)d_out;

    const int smem1 = 2 * 128 * PAD * 2 * sizeof(float);                     // 73728 B
    const int smem3 = (144 * PST + 128 * GTS + 3 * 144) * sizeof(float);     // ~152 KB

    cudaFuncSetAttribute(gemm1_kernel,    cudaFuncAttributeMaxDynamicSharedMemorySize, smem1);
    cudaFuncSetAttribute(attn_mma_kernel, cudaFuncAttributeMaxDynamicSharedMemorySize, smem3);

    nz_zero_kernel<<<1, 1>>>();
    nz_build_kernel<<<(N_ * N_ + 255) / 256, 256>>>(adj);

    dim3 g1(H_, MTOT / 128);   // (8 heads, 266 row tiles)
    gemm1_kernel<<<g1, 256, smem1>>>(x, W, attn_w);

    dim3 g3(H_, B_);
    attn_mma_kernel<<<g3, 512, smem3>>>(out);
}